// round 12
// baseline (speedup 1.0000x reference)
#include <cuda_runtime.h>
#include <cuda_bf16.h>
#include <cuda_fp16.h>
#include <cstdint>

#define NB 8
#define SQ 2048
#define SK 2048
#define DH 512

#define CHUNK_B 32768          // 128x64 bf16 hi+lo tile pair: [hi 16KB][lo 16KB]
#define HCHUNK_B 16384         // 128x64 fp16 single tile
#define SMEM_TILES 1024
#define SMEM_TOTAL 197632      // 1024 + 2*98304 (QK) == 1024 + 4*49152 (PV)

// tcgen05 is arch-accelerated ('a'): only emit in sm_10xa passes.
#if defined(__CUDA_ARCH_FEAT_SM103_ALL) || defined(__CUDA_ARCH_FEAT_SM100_ALL) || \
    defined(__CUDA_ARCH_FEAT_SM101_ALL) ||                                        \
    (defined(__CUDA_ARCH_SPECIFIC__) && (__CUDA_ARCH_SPECIFIC__ >= 1000)) ||      \
    (defined(__CUDA_ARCH_FAMILY_SPECIFIC__) && (__CUDA_ARCH_FAMILY_SPECIFIC__ >= 1000))
#define HAS_TCGEN05 1
#else
#define HAS_TCGEN05 0
#endif

// ------------------------- device scratch (chunked tile layouts) -----------
__device__ float g_ksq[NB * SK];
__device__ __align__(128) char g_Qs[(size_t)NB * 16 * 8 * CHUNK_B];     // 33.5MB bf16 hi/lo
__device__ __align__(128) char g_Ks[(size_t)NB * 16 * 8 * CHUNK_B];     // 33.5MB bf16 hi/lo
__device__ __align__(128) char g_Vs[(size_t)NB * 4 * 32 * HCHUNK_B];    // 16.8MB fp16
__device__ __align__(128) char g_Ws[(size_t)NB * 16 * 32 * HCHUNK_B];   // 67MB fp16

// ------------------------- ptx helpers -------------------------
__device__ __forceinline__ uint32_t smem_u32(const void* p) {
    uint32_t a;
    asm("{ .reg .u64 t; cvta.to.shared.u64 t, %1; cvt.u32.u64 %0, t; }" : "=r"(a) : "l"(p));
    return a;
}
__device__ __forceinline__ uint32_t elect1() {
    uint32_t p;
    asm volatile("{\n\t.reg .pred p;\n\telect.sync _|p, 0xFFFFFFFF;\n\tselp.b32 %0,1,0,p;\n\t}" : "=r"(p));
    return p;
}
__device__ __forceinline__ uint32_t ctarank() {
    uint32_t r;
    asm("mov.u32 %0, %%cluster_ctarank;" : "=r"(r));
    return r;
}
__device__ __forceinline__ void cluster_sync_all() {
    asm volatile("barrier.cluster.arrive.aligned;" ::: "memory");
    asm volatile("barrier.cluster.wait.aligned;" ::: "memory");
}
__device__ __forceinline__ void mbar_init(uint32_t addr, uint32_t cnt) {
    asm volatile("mbarrier.init.shared.b64 [%0], %1;" :: "r"(addr), "r"(cnt) : "memory");
}
__device__ __forceinline__ void mbar_wait(uint32_t mbar, uint32_t parity) {
    asm volatile(
        "{\n\t.reg .pred P;\n\t"
        "W_%=:\n\t"
        "mbarrier.try_wait.parity.acquire.cta.shared::cta.b64 P, [%0], %1, 0x989680;\n\t"
        "@P bra.uni D_%=;\n\t"
        "bra.uni W_%=;\n\t"
        "D_%=:\n\t}"
        :: "r"(mbar), "r"(parity) : "memory");
}
__device__ __forceinline__ void mbar_arrive(uint32_t mbar) {
    asm volatile("mbarrier.arrive.shared.b64 _, [%0];" :: "r"(mbar) : "memory");
}
__device__ __forceinline__ void mbar_arrive_cluster(uint32_t mbar, uint32_t target_rank) {
    asm volatile(
        "{\n\t.reg .b32 r;\n\t"
        "mapa.shared::cluster.u32 r, %0, %1;\n\t"
        "mbarrier.arrive.shared::cluster.b64 _, [r];\n\t}"
        :: "r"(mbar), "r"(target_rank) : "memory");
}
__device__ __forceinline__ void mbar_expect_tx(uint32_t mbar, uint32_t bytes) {
    asm volatile("mbarrier.arrive.expect_tx.shared.b64 _, [%0], %1;"
                 :: "r"(mbar), "r"(bytes) : "memory");
}
__device__ __forceinline__ void bulk_g2s(uint32_t dst, const void* src, uint32_t bytes,
                                         uint32_t mbar) {
    asm volatile(
        "cp.async.bulk.shared::cluster.global.mbarrier::complete_tx::bytes [%0], [%1], %2, [%3];"
        :: "r"(dst), "l"(src), "r"(bytes), "r"(mbar) : "memory");
}

#if HAS_TCGEN05
__device__ __forceinline__ void tmem_alloc_cg2(uint32_t smem_addr, uint32_t ncols) {
    asm volatile("tcgen05.alloc.cta_group::2.sync.aligned.shared::cta.b32 [%0], %1;"
                 :: "r"(smem_addr), "r"(ncols) : "memory");
}
__device__ __forceinline__ void tmem_dealloc_cg2(uint32_t tmem, uint32_t ncols) {
    asm volatile("tcgen05.dealloc.cta_group::2.sync.aligned.b32 %0, %1;" :: "r"(tmem), "r"(ncols));
}
__device__ __forceinline__ void tmem_relinquish_cg2() {
    asm volatile("tcgen05.relinquish_alloc_permit.cta_group::2.sync.aligned;");
}
__device__ __forceinline__ void mma_commit_mc_cg2(uint32_t mbar, uint16_t mask) {
    asm volatile(
        "tcgen05.commit.cta_group::2.mbarrier::arrive::one.shared::cluster.multicast::cluster.b64 "
        "[%0], %1;"
        :: "r"(mbar), "h"(mask) : "memory");
}
__device__ __forceinline__ void tc_fence_after() {
    asm volatile("tcgen05.fence::after_thread_sync;" ::: "memory");
}
__device__ __forceinline__ void tc_wait_ld() {
    asm volatile("tcgen05.wait::ld.sync.aligned;" ::: "memory");
}
__device__ __forceinline__ uint64_t mk_desc(uint32_t addr) {
    // SW128, version=1, SBO=64, LBO=1 (K-major, 128B rows)
    return (2ULL << 61) | (1ULL << 46) | (64ULL << 32) | (1ULL << 16) |
           ((uint64_t)(addr >> 4) & 0x3FFF);
}
__device__ __forceinline__ void mma_f16_ss_cg2(uint32_t d, uint64_t da, uint64_t db,
                                               uint32_t idesc, uint32_t acc) {
    asm volatile(
        "{\n\t.reg .pred p;\n\t"
        "setp.ne.u32 p, %4, 0;\n\t"
        "tcgen05.mma.cta_group::2.kind::f16 [%0], %1, %2, %3, "
        "{%5, %5, %5, %5, %5, %5, %5, %5}, p;\n\t}"
        :: "r"(d), "l"(da), "l"(db), "r"(idesc), "r"(acc), "r"(0u) : "memory");
}
__device__ __forceinline__ void ldtm32(uint32_t* r, uint32_t a) {
    asm volatile(
        "tcgen05.ld.sync.aligned.32x32b.x32.b32 "
        "{%0,%1,%2,%3,%4,%5,%6,%7,%8,%9,%10,%11,%12,%13,%14,%15,"
        "%16,%17,%18,%19,%20,%21,%22,%23,%24,%25,%26,%27,%28,%29,%30,%31}, [%32];"
        : "=r"(r[0]), "=r"(r[1]), "=r"(r[2]), "=r"(r[3]), "=r"(r[4]), "=r"(r[5]), "=r"(r[6]), "=r"(r[7]),
          "=r"(r[8]), "=r"(r[9]), "=r"(r[10]), "=r"(r[11]), "=r"(r[12]), "=r"(r[13]), "=r"(r[14]), "=r"(r[15]),
          "=r"(r[16]), "=r"(r[17]), "=r"(r[18]), "=r"(r[19]), "=r"(r[20]), "=r"(r[21]), "=r"(r[22]), "=r"(r[23]),
          "=r"(r[24]), "=r"(r[25]), "=r"(r[26]), "=r"(r[27]), "=r"(r[28]), "=r"(r[29]), "=r"(r[30]), "=r"(r[31])
        : "r"(a));
}
#endif // HAS_TCGEN05

// idesc cg2 (M=256, N=128, F32 accum): bf16 a/b (QK) and fp16 a/b (PV)
#define IDESC_QK ((1u << 4) | (1u << 7) | (1u << 10) | (16u << 17) | (16u << 24))
#define IDESC_PV ((1u << 4) | (16u << 17) | (16u << 24))

// ---------------------------------------------------------------------------
__device__ __forceinline__ void split8_bf(const float* v, uint32_t* hi, uint32_t* lo) {
    #pragma unroll
    for (int p = 0; p < 4; p++) {
        __nv_bfloat162 h(__float2bfloat16(v[2 * p]), __float2bfloat16(v[2 * p + 1]));
        __nv_bfloat162 l(__float2bfloat16(v[2 * p] - __bfloat162float(h.x)),
                         __float2bfloat16(v[2 * p + 1] - __bfloat162float(h.y)));
        hi[p] = *(uint32_t*)&h;
        lo[p] = *(uint32_t*)&l;
    }
}

// ---------------------------------------------------------------------------
// Fused prep kernel (task-switched by blockIdx.x):
//   [0,4096)      split Q  -> g_Qs (bf16 hi/lo chunks)
//   [4096,8192)   split K  -> g_Ks
//   [8192,16384)  V transpose -> g_Vs (fp16 single chunks)
//   [16384,18432) ksq
// ---------------------------------------------------------------------------
__global__ __launch_bounds__(256) void prep_kernel(const float* __restrict__ Q,
                                                   const float* __restrict__ K,
                                                   const float* __restrict__ V) {
    __shared__ float t[32][33];
    const int bid = blockIdx.x;
    const int tid = threadIdx.x;

    if (bid < 8192) {
        const float* X = (bid < 4096) ? Q : K;
        char* dst = (bid < 4096) ? g_Qs : g_Ks;
        int idx = (bid & 4095) * 256 + tid;
        int mg = idx >> 6;
        int k0 = (idx & 63) * 8;
        int b = mg >> 11, m = mg & 2047;
        int mtile = m >> 7, row = m & 127;
        int kstage = k0 >> 6, colc = k0 & 63;

        float v[8];
        const float* src = X + (size_t)mg * DH + k0;
        *(float4*)(v) = *(const float4*)(src);
        *(float4*)(v + 4) = *(const float4*)(src + 4);
        uint32_t hi[4], lo[4];
        split8_bf(v, hi, lo);

        size_t base = (size_t)((b * 16 + mtile) * 8 + kstage) * CHUNK_B;
        uint32_t off = row * 128 + colc * 2;
        off ^= (off >> 3) & 0x70;
        *(uint4*)(dst + base + off) = make_uint4(hi[0], hi[1], hi[2], hi[3]);
        *(uint4*)(dst + base + 16384 + off) = make_uint4(lo[0], lo[1], lo[2], lo[3]);
    } else if (bid < 16384) {
        // ------- V transpose + fp16 -------
        int r = bid - 8192;
        int b = r >> 10, rem = r & 1023;
        int k0 = (rem >> 4) * 32, d0 = (rem & 15) * 32;
        const float* Vb = V + (size_t)b * SK * DH;
        #pragma unroll
        for (int i = 0; i < 4; i++) {
            int kk = (tid >> 5) + i * 8, dd = tid & 31;
            t[kk][dd] = Vb[(size_t)(k0 + kk) * DH + d0 + dd];
        }
        __syncthreads();
        int d_local = tid >> 3, k_local = (tid & 7) * 4;
        float v[4];
        #pragma unroll
        for (int i = 0; i < 4; i++) v[i] = t[k_local + i][d_local];
        uint32_t hi[2];
        #pragma unroll
        for (int p = 0; p < 2; p++) {
            __half2 hh = __halves2half2(__float2half_rn(v[2 * p]),
                                        __float2half_rn(v[2 * p + 1]));
            hi[p] = *(uint32_t*)&hh;
        }
        int d = d0 + d_local, k = k0 + k_local;
        int ntile = d >> 7, row = d & 127, kstage = k >> 6, colc = k & 63;
        size_t base = (size_t)((b * 4 + ntile) * 32 + kstage) * HCHUNK_B;
        uint32_t off = row * 128 + colc * 2;
        off ^= (off >> 3) & 0x70;
        *(uint2*)(g_Vs + base + off) = make_uint2(hi[0], hi[1]);
    } else {
        int gw = (bid - 16384) * 8 + (tid >> 5);
        int lane = tid & 31;
        const float* row = K + (size_t)gw * DH;
        float s = 0.f;
        #pragma unroll
        for (int i = lane * 4; i < DH; i += 128) {
            float4 v = *(const float4*)(row + i);
            s = fmaf(v.x, v.x, s); s = fmaf(v.y, v.y, s);
            s = fmaf(v.z, v.z, s); s = fmaf(v.w, v.w, s);
        }
        #pragma unroll
        for (int o = 16; o > 0; o >>= 1) s += __shfl_xor_sync(0xffffffffu, s, o);
        if (lane == 0) g_ksq[gw] = s;
    }
}

// ---------------------------------------------------------------------------
// Persistent cg2 GEMM, 256x512 macro tiles (full 512-col TMEM, single D),
// strided tile loop over 74 clusters.
//  QK: A = Q bf16 hi/lo (32KB), B = 4x K bf16 hi/lo rank-halves, 3 MMAs/K16/half.
//  PV: A = W fp16 (16KB),       B = 4x V fp16 rank-halves,       1 MMA /K16/half.
// Stage smem: [A (ACH)] then per half h: QK [Bh 8K][Bl 8K] / PV [B 8K].
// ---------------------------------------------------------------------------
template <int MT, int NX4, int KST, int NBUF_, bool IS_QK>
__global__ __launch_bounds__(256, 1) __cluster_dims__(2, 1, 1)
void gemm5_kernel(const char* __restrict__ Achunks, const char* __restrict__ Bchunks,
                  float* __restrict__ Out, const float* __restrict__ temp) {
    extern __shared__ __align__(1024) char smem[];
    constexpr int LDOUT = NX4 * 512;
    constexpr int TPB = (MT / 2) * NX4;      // macro tiles per batch
    constexpr int TOTAL = NB * TPB;
    constexpr int ACH = IS_QK ? 32768 : 16384;
    constexpr int BCH = IS_QK ? 32768 : 16384;   // full 128-row B chunk in gmem
    constexpr int BHP = IS_QK ? 16384 : 8192;    // per-half smem footprint
    constexpr int STAGE = ACH + 4 * BHP;         // QK 96KB, PV 48KB

    const int tid = threadIdx.x;
    const int wid = tid >> 5, lid = tid & 31;

#if HAS_TCGEN05
    const uint32_t rank = ctarank();
    const int cluster = blockIdx.x >> 1;
    const int NCLUST = gridDim.x >> 1;
    const int nt = (cluster < TOTAL) ? (TOTAL - cluster + NCLUST - 1) / NCLUST : 0;

    const uint32_t sbase = smem_u32(smem);
    // mbars: full[i]@+8+8i  empty[i]@+48+8i  peerfull[i]@+88+8i (i<4)
    //        done@+128  efree@+136
    if (wid == 0) {
        tmem_alloc_cg2(sbase, 512);
        tmem_relinquish_cg2();
    }
    if (tid == 0) {
        #pragma unroll
        for (int i = 0; i < NBUF_; i++) {
            mbar_init(sbase + 8 + i * 8, 1);
            mbar_init(sbase + 48 + i * 8, 1);
            mbar_init(sbase + 88 + i * 8, 1);
        }
        mbar_init(sbase + 128, 1);
        mbar_init(sbase + 136, 8);
    }
    __syncthreads();
    cluster_sync_all();
    uint32_t tmem;
    asm volatile("ld.shared.b32 %0, [%1];" : "=r"(tmem) : "r"(sbase));

    if (wid == 1 && elect1()) {
        // ---------------- producer ----------------
        for (int gs = 0; gs < nt * KST; gs++) {
            const int it = gs / KST, s = gs % KST;
            const int T = cluster + it * NCLUST;
            const int b = T / TPB, rem = T % TPB;
            const int mypair = rem / NX4, nx4 = rem % NX4;
            const int my = mypair * 2 + (int)rank;
            const int buf = gs % NBUF_;
            if (gs >= NBUF_) mbar_wait(sbase + 48 + buf * 8, ((gs - NBUF_) / NBUF_) & 1);
            uint32_t fm = sbase + 8 + buf * 8;
            uint32_t dst = sbase + SMEM_TILES + buf * STAGE;
            mbar_expect_tx(fm, STAGE);
            bulk_g2s(dst, Achunks + (size_t)((b * MT + my) * KST + s) * ACH, ACH, fm);
            #pragma unroll
            for (int h = 0; h < 4; h++) {
                const char* ch =
                    Bchunks + (size_t)((b * NX4 * 4 + nx4 * 4 + h) * KST + s) * BCH;
                if (IS_QK) {
                    bulk_g2s(dst + ACH + h * BHP,        ch + rank * 8192, 8192, fm);
                    bulk_g2s(dst + ACH + h * BHP + 8192, ch + 16384 + rank * 8192, 8192, fm);
                } else {
                    bulk_g2s(dst + ACH + h * BHP, ch + rank * 8192, 8192, fm);
                }
            }
        }
    } else if (wid == 0 && elect1()) {
        if (rank == 1) {
            // ---------------- full-barrier forwarder ----------------
            for (int gs = 0; gs < nt * KST; gs++) {
                const int buf = gs % NBUF_;
                mbar_wait(sbase + 8 + buf * 8, (gs / NBUF_) & 1);
                mbar_arrive_cluster(sbase + 88 + buf * 8, 0);
            }
        } else {
            // ---------------- cg2 MMA issuer (rank 0) ----------------
            for (int it = 0; it < nt; it++) {
                if (it >= 1) {
                    mbar_wait(sbase + 136, (it - 1) & 1);
                    tc_fence_after();
                }
                for (int s = 0; s < KST; s++) {
                    const int gs = it * KST + s;
                    const int buf = gs % NBUF_;
                    const uint32_t par = (gs / NBUF_) & 1;
                    mbar_wait(sbase + 8 + buf * 8, par);
                    mbar_wait(sbase + 88 + buf * 8, par);
                    uint32_t tb = sbase + SMEM_TILES + buf * STAGE;
                    #pragma unroll
                    for (int h = 0; h < 4; h++) {
                        const uint32_t dh = tmem + h * 128;
                        if (IS_QK) {
                            uint64_t dAh = mk_desc(tb);
                            uint64_t dAl = mk_desc(tb + 16384);
                            uint64_t dBh = mk_desc(tb + ACH + h * BHP);
                            uint64_t dBl = mk_desc(tb + ACH + h * BHP + 8192);
                            #pragma unroll
                            for (int ks = 0; ks < 4; ks++) {
                                uint32_t acc0 = (s == 0 && ks == 0) ? 0u : 1u;
                                mma_f16_ss_cg2(dh, dAh + ks * 2, dBh + ks * 2, IDESC_QK, acc0);
                                mma_f16_ss_cg2(dh, dAh + ks * 2, dBl + ks * 2, IDESC_QK, 1u);
                                mma_f16_ss_cg2(dh, dAl + ks * 2, dBh + ks * 2, IDESC_QK, 1u);
                            }
                        } else {
                            uint64_t dA = mk_desc(tb);
                            uint64_t dB = mk_desc(tb + ACH + h * BHP);
                            #pragma unroll
                            for (int ks = 0; ks < 4; ks++) {
                                uint32_t acc0 = (s == 0 && ks == 0) ? 0u : 1u;
                                mma_f16_ss_cg2(dh, dA + ks * 2, dB + ks * 2, IDESC_PV, acc0);
                            }
                        }
                    }
                    mma_commit_mc_cg2(sbase + 48 + buf * 8, 0x3);
                }
                mma_commit_mc_cg2(sbase + 128, 0x3);   // done on both CTAs
            }
        }
    } else if (wid >= 4) {
        // ---------------- epilogue warps (4..7, both CTAs) ----------------
        const int wsub = wid - 4;
        const float invT = IS_QK ? 1.0f / temp[0] : 1.0f;
        for (int it = 0; it < nt; it++) {
            const int T = cluster + it * NCLUST;
            const int b = T / TPB, rem = T % TPB;
            const int mypair = rem / NX4, nx4 = rem % NX4;
            const int n0 = nx4 * 512;
            const int m = mypair * 256 + (int)rank * 128 + wsub * 32 + lid;
            mbar_wait(sbase + 128, it & 1);
            tc_fence_after();
            #pragma unroll
            for (int cb = 0; cb < 512; cb += 32) {
                uint32_t r[32];
                ldtm32(r, tmem + cb);
                tc_wait_ld();
                float* op = Out + (size_t)b * SQ * LDOUT + (size_t)m * LDOUT + n0 + cb;
                if (IS_QK) {
                    const float* kq = g_ksq + b * SK + n0 + cb;
                    #pragma unroll
                    for (int cc = 0; cc < 32; cc += 4) {
                        float4 o;
                        o.x = (2.f * __uint_as_float(r[cc + 0]) - kq[cc + 0]) * invT;
                        o.y = (2.f * __uint_as_float(r[cc + 1]) - kq[cc + 1]) * invT;
                        o.z = (2.f * __uint_as_float(r[cc + 2]) - kq[cc + 2]) * invT;
                        o.w = (2.f * __uint_as_float(r[cc + 3]) - kq[cc + 3]) * invT;
                        *(float4*)(op + cc) = o;
                    }
                } else {
                    #pragma unroll
                    for (int cc = 0; cc < 32; cc += 4) {
                        float4 o;
                        o.x = __uint_as_float(r[cc + 0]);
                        o.y = __uint_as_float(r[cc + 1]);
                        o.z = __uint_as_float(r[cc + 2]);
                        o.w = __uint_as_float(r[cc + 3]);
                        *(float4*)(op + cc) = o;
                    }
                }
            }
            if (elect1()) {
                if (rank == 0) mbar_arrive(sbase + 136);
                else           mbar_arrive_cluster(sbase + 136, 0);
            }
        }
    }

    __syncthreads();
    if (wid == 0) tmem_dealloc_cg2(tmem, 512);
    cluster_sync_all();

#else  // ---------------- naive correct fallback (plain sm_103 pass; unused) ----
    const int cluster = blockIdx.x >> 1;
    const int rank = blockIdx.x & 1;
    const int NCLUST = gridDim.x >> 1;
    const int nt = (cluster < TOTAL) ? (TOTAL - cluster + NCLUST - 1) / NCLUST : 0;
    const float invT = IS_QK ? 1.f / temp[0] : 1.f;
    for (int it = 0; it < nt; it++) {
        const int T = cluster + it * NCLUST;
        const int b = T / TPB, rem = T % TPB;
        const int mypair = rem / NX4, nx4 = rem % NX4;
        const int my = mypair * 2 + rank;
        const int m0 = my * 128, n0 = nx4 * 512;
        const char* ca0 = Achunks + (size_t)(b * MT + my) * KST * ACH;
        for (int e = tid; e < 128 * 512; e += 256) {
            int i = e >> 9, j = e & 511;
            const char* cb0 =
                Bchunks + (size_t)(b * NX4 * 4 + nx4 * 4 + (j >> 7)) * KST * BCH;
            int jj = j & 127;
            float acc = 0.f;
            for (int s = 0; s < KST; s++) {
                const char* ca = ca0 + (size_t)s * ACH;
                const char* cb = cb0 + (size_t)s * BCH;
                for (int k = 0; k < 64; k++) {
                    uint32_t oa = i * 128 + k * 2; oa ^= (oa >> 3) & 0x70;
                    uint32_t ob = jj * 128 + k * 2; ob ^= (ob >> 3) & 0x70;
                    float a, bb;
                    if (IS_QK) {
                        a = __bfloat162float(*(const __nv_bfloat16*)(ca + oa)) +
                            __bfloat162float(*(const __nv_bfloat16*)(ca + 16384 + oa));
                        bb = __bfloat162float(*(const __nv_bfloat16*)(cb + ob)) +
                             __bfloat162float(*(const __nv_bfloat16*)(cb + 16384 + ob));
                    } else {
                        a = __half2float(*(const __half*)(ca + oa));
                        bb = __half2float(*(const __half*)(cb + ob));
                    }
                    acc = fmaf(a, bb, acc);
                }
            }
            float* op = Out + (size_t)b * SQ * LDOUT + (size_t)(m0 + i) * LDOUT + n0 + j;
            *op = IS_QK ? (2.f * acc - g_ksq[b * SK + n0 + j]) * invT : acc;
        }
        __syncthreads();
    }
#endif
}

// ---------------------------------------------------------------------------
// softmax (in-place fp32) + write fp16 chunked W tiles for PV
// ---------------------------------------------------------------------------
__global__ __launch_bounds__(256) void softmax_kernel(float* __restrict__ W) {
    const int rowg = blockIdx.x;
    float* r = W + (size_t)rowg * SK;
    const int tid = threadIdx.x;

    float vals[8];
    *(float4*)(vals) = *(const float4*)(r + tid * 8);
    *(float4*)(vals + 4) = *(const float4*)(r + tid * 8 + 4);
    float m = vals[0];
    #pragma unroll
    for (int i = 1; i < 8; i++) m = fmaxf(m, vals[i]);

    __shared__ float red[8];
    #pragma unroll
    for (int o = 16; o > 0; o >>= 1) m = fmaxf(m, __shfl_xor_sync(0xffffffffu, m, o));
    if ((tid & 31) == 0) red[tid >> 5] = m;
    __syncthreads();
    m = red[0];
    #pragma unroll
    for (int w = 1; w < 8; w++) m = fmaxf(m, red[w]);
    __syncthreads();

    float s = 0.f;
    #pragma unroll
    for (int i = 0; i < 8; i++) {
        vals[i] = __expf(vals[i] - m);
        s += vals[i];
    }
    #pragma unroll
    for (int o = 16; o > 0; o >>= 1) s += __shfl_xor_sync(0xffffffffu, s, o);
    if ((tid & 31) == 0) red[tid >> 5] = s;
    __syncthreads();
    s = red[0];
    #pragma unroll
    for (int w = 1; w < 8; w++) s += red[w];

    const float inv = 1.0f / s;
    #pragma unroll
    for (int i = 0; i < 8; i++) vals[i] *= inv;
    *(float4*)(r + tid * 8) = *(float4*)(vals);
    *(float4*)(r + tid * 8 + 4) = *(float4*)(vals + 4);

    uint32_t w4[4];
    #pragma unroll
    for (int p = 0; p < 4; p++) {
        __half2 hh = __halves2half2(__float2half_rn(vals[2 * p]),
                                    __float2half_rn(vals[2 * p + 1]));
        w4[p] = *(uint32_t*)&hh;
    }
    const int b = rowg >> 11, q = rowg & 2047;
    const int mtile = q >> 7, row = q & 127;
    const int kstage = tid >> 3, colc = (tid * 8) & 63;
    size_t base = (size_t)((b * 16 + mtile) * 32 + kstage) * HCHUNK_B;
    uint32_t off = row * 128 + colc * 2;
    off ^= (off >> 3) & 0x70;
    *(uint4*)(g_Ws + base + off) = make_uint4(w4[0], w4[1], w4[2], w4[3]);
}

// ---------------------------------------------------------------------------
extern "C" void kernel_launch(void* const* d_in, const int* in_sizes, int n_in,
                              void* d_out, int out_size) {
    const float* Q = (const float*)d_in[0];
    const float* K = (const float*)d_in[1];
    const float* V = (const float*)d_in[2];
    const float* T = (const float*)d_in[3];

    float* attended = (float*)d_out;                        // [B,SQ,DH]
    float* weights  = (float*)d_out + (size_t)NB * SQ * DH; // [B,SQ,SK]

    void *qs, *ks, *vs, *ws;
    cudaGetSymbolAddress(&qs, g_Qs);
    cudaGetSymbolAddress(&ks, g_Ks);
    cudaGetSymbolAddress(&vs, g_Vs);
    cudaGetSymbolAddress(&ws, g_Ws);

    cudaFuncSetAttribute((const void*)gemm5_kernel<16, 4, 8, 2, true>,
                         cudaFuncAttributeMaxDynamicSharedMemorySize, SMEM_TOTAL);
    cudaFuncSetAttribute((const void*)gemm5_kernel<16, 1, 32, 4, false>,
                         cudaFuncAttributeMaxDynamicSharedMemorySize, SMEM_TOTAL);

    // 1) fused prep (splits + vsplit + ksq)
    prep_kernel<<<18432, 256>>>(Q, K, V);

    // 2) logits = (2 q.k - ksq)/T — 256 macro tiles (256x512) over 74 clusters
    gemm5_kernel<16, 4, 8, 2, true><<<148, 256, SMEM_TOTAL>>>(
        (const char*)qs, (const char*)ks, weights, T);

    // 3) softmax in-place + fp16 chunked W
    softmax_kernel<<<NB * SQ, 256>>>(weights);

    // 4) attended = W @ V — 64 macro tiles (256x512) over 74 clusters
    gemm5_kernel<16, 1, 32, 4, false><<<148, 256, SMEM_TOTAL>>>(
        (const char*)ws, (const char*)vs, attended, nullptr);
}

// round 13
// speedup vs baseline: 1.2548x; 1.2548x over previous
#include <cuda_runtime.h>
#include <cuda_bf16.h>
#include <cuda_fp16.h>
#include <cstdint>

#define NB 8
#define SQ 2048
#define SK 2048
#define DH 512

#define CHUNK_B 32768          // 128x64 bf16 hi+lo tile pair: [hi 16KB][lo 16KB]
#define HCHUNK_B 16384         // 128x64 fp16 single tile
#define SMEM_TILES 1024
#define SMEM_TOTAL 197632      // 1024 + 3*65536 (QK) == 1024 + 6*32768 (PV)

// tcgen05 is arch-accelerated ('a'): only emit in sm_10xa passes.
#if defined(__CUDA_ARCH_FEAT_SM103_ALL) || defined(__CUDA_ARCH_FEAT_SM100_ALL) || \
    defined(__CUDA_ARCH_FEAT_SM101_ALL) ||                                        \
    (defined(__CUDA_ARCH_SPECIFIC__) && (__CUDA_ARCH_SPECIFIC__ >= 1000)) ||      \
    (defined(__CUDA_ARCH_FAMILY_SPECIFIC__) && (__CUDA_ARCH_FAMILY_SPECIFIC__ >= 1000))
#define HAS_TCGEN05 1
#else
#define HAS_TCGEN05 0
#endif

// ------------------------- device scratch (chunked tile layouts) -----------
__device__ float g_ksq[NB * SK];
__device__ __align__(128) char g_Qs[(size_t)NB * 16 * 8 * CHUNK_B];     // 33.5MB bf16 hi/lo
__device__ __align__(128) char g_Ks[(size_t)NB * 16 * 8 * CHUNK_B];     // 33.5MB bf16 hi/lo
__device__ __align__(128) char g_Vs[(size_t)NB * 4 * 32 * HCHUNK_B];    // 16.8MB fp16
__device__ __align__(128) char g_Ws[(size_t)NB * 16 * 32 * HCHUNK_B];   // 67MB fp16

// ------------------------- ptx helpers -------------------------
__device__ __forceinline__ uint32_t smem_u32(const void* p) {
    uint32_t a;
    asm("{ .reg .u64 t; cvta.to.shared.u64 t, %1; cvt.u32.u64 %0, t; }" : "=r"(a) : "l"(p));
    return a;
}
__device__ __forceinline__ uint32_t elect1() {
    uint32_t p;
    asm volatile("{\n\t.reg .pred p;\n\telect.sync _|p, 0xFFFFFFFF;\n\tselp.b32 %0,1,0,p;\n\t}" : "=r"(p));
    return p;
}
__device__ __forceinline__ uint32_t ctarank() {
    uint32_t r;
    asm("mov.u32 %0, %%cluster_ctarank;" : "=r"(r));
    return r;
}
__device__ __forceinline__ void cluster_sync_all() {
    asm volatile("barrier.cluster.arrive.aligned;" ::: "memory");
    asm volatile("barrier.cluster.wait.aligned;" ::: "memory");
}
__device__ __forceinline__ void mbar_init(uint32_t addr, uint32_t cnt) {
    asm volatile("mbarrier.init.shared.b64 [%0], %1;" :: "r"(addr), "r"(cnt) : "memory");
}
__device__ __forceinline__ void mbar_wait(uint32_t mbar, uint32_t parity) {
    asm volatile(
        "{\n\t.reg .pred P;\n\t"
        "W_%=:\n\t"
        "mbarrier.try_wait.parity.acquire.cta.shared::cta.b64 P, [%0], %1, 0x989680;\n\t"
        "@P bra.uni D_%=;\n\t"
        "bra.uni W_%=;\n\t"
        "D_%=:\n\t}"
        :: "r"(mbar), "r"(parity) : "memory");
}
__device__ __forceinline__ void mbar_arrive(uint32_t mbar) {
    asm volatile("mbarrier.arrive.shared.b64 _, [%0];" :: "r"(mbar) : "memory");
}
__device__ __forceinline__ void mbar_arrive_cluster(uint32_t mbar, uint32_t target_rank) {
    asm volatile(
        "{\n\t.reg .b32 r;\n\t"
        "mapa.shared::cluster.u32 r, %0, %1;\n\t"
        "mbarrier.arrive.shared::cluster.b64 _, [r];\n\t}"
        :: "r"(mbar), "r"(target_rank) : "memory");
}
__device__ __forceinline__ void mbar_expect_tx(uint32_t mbar, uint32_t bytes) {
    asm volatile("mbarrier.arrive.expect_tx.shared.b64 _, [%0], %1;"
                 :: "r"(mbar), "r"(bytes) : "memory");
}
__device__ __forceinline__ void bulk_g2s(uint32_t dst, const void* src, uint32_t bytes,
                                         uint32_t mbar) {
    asm volatile(
        "cp.async.bulk.shared::cluster.global.mbarrier::complete_tx::bytes [%0], [%1], %2, [%3];"
        :: "r"(dst), "l"(src), "r"(bytes), "r"(mbar) : "memory");
}

#if HAS_TCGEN05
__device__ __forceinline__ void tmem_alloc_cg2(uint32_t smem_addr, uint32_t ncols) {
    asm volatile("tcgen05.alloc.cta_group::2.sync.aligned.shared::cta.b32 [%0], %1;"
                 :: "r"(smem_addr), "r"(ncols) : "memory");
}
__device__ __forceinline__ void tmem_dealloc_cg2(uint32_t tmem, uint32_t ncols) {
    asm volatile("tcgen05.dealloc.cta_group::2.sync.aligned.b32 %0, %1;" :: "r"(tmem), "r"(ncols));
}
__device__ __forceinline__ void tmem_relinquish_cg2() {
    asm volatile("tcgen05.relinquish_alloc_permit.cta_group::2.sync.aligned;");
}
__device__ __forceinline__ void mma_commit_mc_cg2(uint32_t mbar, uint16_t mask) {
    asm volatile(
        "tcgen05.commit.cta_group::2.mbarrier::arrive::one.shared::cluster.multicast::cluster.b64 "
        "[%0], %1;"
        :: "r"(mbar), "h"(mask) : "memory");
}
__device__ __forceinline__ void tc_fence_after() {
    asm volatile("tcgen05.fence::after_thread_sync;" ::: "memory");
}
__device__ __forceinline__ void tc_wait_ld() {
    asm volatile("tcgen05.wait::ld.sync.aligned;" ::: "memory");
}
__device__ __forceinline__ uint64_t mk_desc(uint32_t addr) {
    // SW128, version=1, SBO=64, LBO=1 (K-major, 128B rows)
    return (2ULL << 61) | (1ULL << 46) | (64ULL << 32) | (1ULL << 16) |
           ((uint64_t)(addr >> 4) & 0x3FFF);
}
__device__ __forceinline__ void mma_f16_ss_cg2(uint32_t d, uint64_t da, uint64_t db,
                                               uint32_t idesc, uint32_t acc) {
    asm volatile(
        "{\n\t.reg .pred p;\n\t"
        "setp.ne.u32 p, %4, 0;\n\t"
        "tcgen05.mma.cta_group::2.kind::f16 [%0], %1, %2, %3, "
        "{%5, %5, %5, %5, %5, %5, %5, %5}, p;\n\t}"
        :: "r"(d), "l"(da), "l"(db), "r"(idesc), "r"(acc), "r"(0u) : "memory");
}
__device__ __forceinline__ void ldtm32(uint32_t* r, uint32_t a) {
    asm volatile(
        "tcgen05.ld.sync.aligned.32x32b.x32.b32 "
        "{%0,%1,%2,%3,%4,%5,%6,%7,%8,%9,%10,%11,%12,%13,%14,%15,"
        "%16,%17,%18,%19,%20,%21,%22,%23,%24,%25,%26,%27,%28,%29,%30,%31}, [%32];"
        : "=r"(r[0]), "=r"(r[1]), "=r"(r[2]), "=r"(r[3]), "=r"(r[4]), "=r"(r[5]), "=r"(r[6]), "=r"(r[7]),
          "=r"(r[8]), "=r"(r[9]), "=r"(r[10]), "=r"(r[11]), "=r"(r[12]), "=r"(r[13]), "=r"(r[14]), "=r"(r[15]),
          "=r"(r[16]), "=r"(r[17]), "=r"(r[18]), "=r"(r[19]), "=r"(r[20]), "=r"(r[21]), "=r"(r[22]), "=r"(r[23]),
          "=r"(r[24]), "=r"(r[25]), "=r"(r[26]), "=r"(r[27]), "=r"(r[28]), "=r"(r[29]), "=r"(r[30]), "=r"(r[31])
        : "r"(a));
}
#endif // HAS_TCGEN05

// idesc cg2 (M=256, N=128, F32 accum): bf16 a/b (QK) and fp16 a/b (PV)
#define IDESC_QK ((1u << 4) | (1u << 7) | (1u << 10) | (16u << 17) | (16u << 24))
#define IDESC_PV ((1u << 4) | (16u << 17) | (16u << 24))

// ---------------------------------------------------------------------------
__device__ __forceinline__ void split8_bf(const float* v, uint32_t* hi, uint32_t* lo) {
    #pragma unroll
    for (int p = 0; p < 4; p++) {
        __nv_bfloat162 h(__float2bfloat16(v[2 * p]), __float2bfloat16(v[2 * p + 1]));
        __nv_bfloat162 l(__float2bfloat16(v[2 * p] - __bfloat162float(h.x)),
                         __float2bfloat16(v[2 * p + 1] - __bfloat162float(h.y)));
        hi[p] = *(uint32_t*)&h;
        lo[p] = *(uint32_t*)&l;
    }
}

// ---------------------------------------------------------------------------
// Fused prep kernel (task-switched by blockIdx.x):
//   [0,4096)      split Q  -> g_Qs (bf16 hi/lo chunks)
//   [4096,8192)   split K  -> g_Ks  + fused ksq row reduction
//   [8192,16384)  V transpose -> g_Vs (fp16 single chunks)
// ---------------------------------------------------------------------------
__global__ __launch_bounds__(256) void prep_kernel(const float* __restrict__ Q,
                                                   const float* __restrict__ K,
                                                   const float* __restrict__ V) {
    __shared__ float t[32][33];
    const int bid = blockIdx.x;
    const int tid = threadIdx.x;

    if (bid < 8192) {
        const bool isK = (bid >= 4096);
        const float* X = isK ? K : Q;
        char* dst = isK ? g_Ks : g_Qs;
        int idx = (bid & 4095) * 256 + tid;
        int mg = idx >> 6;                 // global row; 64 threads per row
        int k0 = (idx & 63) * 8;
        int b = mg >> 11, m = mg & 2047;
        int mtile = m >> 7, row = m & 127;
        int kstage = k0 >> 6, colc = k0 & 63;

        float v[8];
        const float* src = X + (size_t)mg * DH + k0;
        *(float4*)(v) = *(const float4*)(src);
        *(float4*)(v + 4) = *(const float4*)(src + 4);
        uint32_t hi[4], lo[4];
        split8_bf(v, hi, lo);

        size_t base = (size_t)((b * 16 + mtile) * 8 + kstage) * CHUNK_B;
        uint32_t off = row * 128 + colc * 2;
        off ^= (off >> 3) & 0x70;
        *(uint4*)(dst + base + off) = make_uint4(hi[0], hi[1], hi[2], hi[3]);
        *(uint4*)(dst + base + 16384 + off) = make_uint4(lo[0], lo[1], lo[2], lo[3]);

        if (isK) {
            // fused ksq: block covers 4 rows, 64 threads (2 warps) per row
            float s = 0.f;
            #pragma unroll
            for (int i = 0; i < 8; i++) s = fmaf(v[i], v[i], s);
            #pragma unroll
            for (int o = 16; o > 0; o >>= 1) s += __shfl_xor_sync(0xffffffffu, s, o);
            __shared__ float wsum[8];
            if ((tid & 31) == 0) wsum[tid >> 5] = s;
            __syncthreads();
            if (tid < 4) {
                int mg0 = ((bid & 4095) * 256) >> 6;   // first row of block
                g_ksq[mg0 + tid] = wsum[2 * tid] + wsum[2 * tid + 1];
            }
        }
    } else {
        // ------- V transpose + fp16 -------
        int r = bid - 8192;
        int b = r >> 10, rem = r & 1023;
        int k0 = (rem >> 4) * 32, d0 = (rem & 15) * 32;
        const float* Vb = V + (size_t)b * SK * DH;
        #pragma unroll
        for (int i = 0; i < 4; i++) {
            int kk = (tid >> 5) + i * 8, dd = tid & 31;
            t[kk][dd] = Vb[(size_t)(k0 + kk) * DH + d0 + dd];
        }
        __syncthreads();
        int d_local = tid >> 3, k_local = (tid & 7) * 4;
        float v[4];
        #pragma unroll
        for (int i = 0; i < 4; i++) v[i] = t[k_local + i][d_local];
        uint32_t hi[2];
        #pragma unroll
        for (int p = 0; p < 2; p++) {
            __half2 hh = __halves2half2(__float2half_rn(v[2 * p]),
                                        __float2half_rn(v[2 * p + 1]));
            hi[p] = *(uint32_t*)&hh;
        }
        int d = d0 + d_local, k = k0 + k_local;
        int ntile = d >> 7, row = d & 127, kstage = k >> 6, colc = k & 63;
        size_t base = (size_t)((b * 4 + ntile) * 32 + kstage) * HCHUNK_B;
        uint32_t off = row * 128 + colc * 2;
        off ^= (off >> 3) & 0x70;
        *(uint2*)(g_Vs + base + off) = make_uint2(hi[0], hi[1]);
    }
}

// ---------------------------------------------------------------------------
// Persistent cg2 GEMM, 256x256 macro tiles, strided tile loop over 74 clusters.
//  QK: A = Q bf16 hi/lo (32KB), B = K bf16 hi/lo (rank-half 16KB), 3 MMAs/K16/half.
//  PV: A = W fp16 (16KB),       B = V fp16 (rank-half 8KB),        1 MMA /K16/half.
// ---------------------------------------------------------------------------
template <int MT, int NXT2, int KST, int NBUF_, bool IS_QK>
__global__ __launch_bounds__(256, 1) __cluster_dims__(2, 1, 1)
void gemm5_kernel(const char* __restrict__ Achunks, const char* __restrict__ Bchunks,
                  float* __restrict__ Out, const float* __restrict__ temp) {
    extern __shared__ __align__(1024) char smem[];
    constexpr int LDOUT = NXT2 * 256;
    constexpr int TPB = (MT / 2) * NXT2;     // macro tiles per batch
    constexpr int TOTAL = NB * TPB;
    constexpr int ACH = IS_QK ? 32768 : 16384;
    constexpr int BCH = IS_QK ? 32768 : 16384;   // full 128-row chunk size in gmem
    constexpr int BSL = BCH / 4;                 // one hi-or-lo rank-half slice (8K/4K)
    constexpr int STAGE = ACH + BCH;             // per-CTA stage bytes

    const int tid = threadIdx.x;
    const int wid = tid >> 5, lid = tid & 31;

#if HAS_TCGEN05
    const uint32_t rank = ctarank();
    const int cluster = blockIdx.x >> 1;
    const int NCLUST = gridDim.x >> 1;
    const int nt = (cluster < TOTAL) ? (TOTAL - cluster + NCLUST - 1) / NCLUST : 0;

    const uint32_t sbase = smem_u32(smem);
    // mbars: full[i]@+8+8i  empty[i]@+64+8i  peerfull[i]@+120+8i (i<6)
    //        done[2]@+176,184  efree[2]@+192,200
    if (wid == 0) {
        tmem_alloc_cg2(sbase, 512);
        tmem_relinquish_cg2();
    }
    if (tid == 0) {
        #pragma unroll
        for (int i = 0; i < NBUF_; i++) {
            mbar_init(sbase + 8 + i * 8, 1);
            mbar_init(sbase + 64 + i * 8, 1);
            mbar_init(sbase + 120 + i * 8, 1);
        }
        mbar_init(sbase + 176, 1);
        mbar_init(sbase + 184, 1);
        mbar_init(sbase + 192, 8);
        mbar_init(sbase + 200, 8);
    }
    __syncthreads();
    cluster_sync_all();
    uint32_t tmem;
    asm volatile("ld.shared.b32 %0, [%1];" : "=r"(tmem) : "r"(sbase));

    if (wid == 1 && elect1()) {
        // ---------------- producer ----------------
        for (int gs = 0; gs < nt * KST; gs++) {
            const int it = gs / KST, s = gs % KST;
            const int T = cluster + it * NCLUST;
            const int b = T / TPB, rem = T % TPB;
            const int mypair = rem / NXT2, nx2 = rem % NXT2;
            const int my = mypair * 2 + (int)rank;
            const int buf = gs % NBUF_;
            if (gs >= NBUF_) mbar_wait(sbase + 64 + buf * 8, ((gs - NBUF_) / NBUF_) & 1);
            uint32_t fm = sbase + 8 + buf * 8;
            uint32_t dst = sbase + SMEM_TILES + buf * STAGE;
            mbar_expect_tx(fm, STAGE);
            bulk_g2s(dst, Achunks + (size_t)((b * MT + my) * KST + s) * ACH, ACH, fm);
            const char* c0 = Bchunks + (size_t)((b * NXT2 * 2 + nx2 * 2) * KST + s) * BCH;
            const char* c1 = c0 + (size_t)KST * BCH;
            if (IS_QK) {
                bulk_g2s(dst + ACH,           c0 + rank * BSL, BSL, fm);
                bulk_g2s(dst + ACH + BSL,     c0 + 2 * BSL + rank * BSL, BSL, fm);
                bulk_g2s(dst + ACH + 2 * BSL, c1 + rank * BSL, BSL, fm);
                bulk_g2s(dst + ACH + 3 * BSL, c1 + 2 * BSL + rank * BSL, BSL, fm);
            } else {
                bulk_g2s(dst + ACH,            c0 + rank * 8192, 8192, fm);
                bulk_g2s(dst + ACH + 8192,     c1 + rank * 8192, 8192, fm);
            }
        }
    } else if (wid == 0 && elect1()) {
        if (rank == 1) {
            // ---------------- full-barrier forwarder ----------------
            for (int gs = 0; gs < nt * KST; gs++) {
                const int buf = gs % NBUF_;
                mbar_wait(sbase + 8 + buf * 8, (gs / NBUF_) & 1);
                mbar_arrive_cluster(sbase + 120 + buf * 8, 0);
            }
        } else {
            // ---------------- cg2 MMA issuer (rank 0) ----------------
            for (int it = 0; it < nt; it++) {
                const uint32_t dbuf = tmem + (it & 1) * 256;
                if (it >= 2) {
                    mbar_wait(sbase + 192 + (it & 1) * 8, ((it >> 1) - 1) & 1);
                    tc_fence_after();
                }
                for (int s = 0; s < KST; s++) {
                    const int gs = it * KST + s;
                    const int buf = gs % NBUF_;
                    const uint32_t par = (gs / NBUF_) & 1;
                    mbar_wait(sbase + 8 + buf * 8, par);
                    mbar_wait(sbase + 120 + buf * 8, par);
                    uint32_t tb = sbase + SMEM_TILES + buf * STAGE;
                    #pragma unroll
                    for (int h = 0; h < 2; h++) {
                        const uint32_t dh = dbuf + h * 128;
                        if (IS_QK) {
                            uint64_t dAh = mk_desc(tb);
                            uint64_t dAl = mk_desc(tb + 16384);
                            uint64_t dBh = mk_desc(tb + ACH + 2 * h * BSL);
                            uint64_t dBl = mk_desc(tb + ACH + (2 * h + 1) * BSL);
                            #pragma unroll
                            for (int ks = 0; ks < 4; ks++) {
                                uint32_t acc0 = (s == 0 && ks == 0) ? 0u : 1u;
                                mma_f16_ss_cg2(dh, dAh + ks * 2, dBh + ks * 2, IDESC_QK, acc0);
                                mma_f16_ss_cg2(dh, dAh + ks * 2, dBl + ks * 2, IDESC_QK, 1u);
                                mma_f16_ss_cg2(dh, dAl + ks * 2, dBh + ks * 2, IDESC_QK, 1u);
                            }
                        } else {
                            uint64_t dA = mk_desc(tb);
                            uint64_t dB = mk_desc(tb + ACH + h * 8192);
                            #pragma unroll
                            for (int ks = 0; ks < 4; ks++) {
                                uint32_t acc0 = (s == 0 && ks == 0) ? 0u : 1u;
                                mma_f16_ss_cg2(dh, dA + ks * 2, dB + ks * 2, IDESC_PV, acc0);
                            }
                        }
                    }
                    mma_commit_mc_cg2(sbase + 64 + buf * 8, 0x3);
                }
                mma_commit_mc_cg2(sbase + 176 + (it & 1) * 8, 0x3);
            }
        }
    } else if (wid >= 4) {
        // ---------------- epilogue warps (4..7, both CTAs) ----------------
        const int wsub = wid - 4;
        const float invT = IS_QK ? 1.0f / temp[0] : 1.0f;
        for (int it = 0; it < nt; it++) {
            const int T = cluster + it * NCLUST;
            const int b = T / TPB, rem = T % TPB;
            const int mypair = rem / NXT2, nx2 = rem % NXT2;
            const int n0 = nx2 * 256;
            const int m = mypair * 256 + (int)rank * 128 + wsub * 32 + lid;
            mbar_wait(sbase + 176 + (it & 1) * 8, (it >> 1) & 1);
            tc_fence_after();
            const uint32_t dbuf = tmem + (it & 1) * 256;
            #pragma unroll
            for (int cb = 0; cb < 256; cb += 32) {
                uint32_t r[32];
                ldtm32(r, dbuf + cb);
                tc_wait_ld();
                float* op = Out + (size_t)b * SQ * LDOUT + (size_t)m * LDOUT + n0 + cb;
                if (IS_QK) {
                    const float* kq = g_ksq + b * SK + n0 + cb;
                    #pragma unroll
                    for (int cc = 0; cc < 32; cc += 4) {
                        float4 o;
                        o.x = (2.f * __uint_as_float(r[cc + 0]) - kq[cc + 0]) * invT;
                        o.y = (2.f * __uint_as_float(r[cc + 1]) - kq[cc + 1]) * invT;
                        o.z = (2.f * __uint_as_float(r[cc + 2]) - kq[cc + 2]) * invT;
                        o.w = (2.f * __uint_as_float(r[cc + 3]) - kq[cc + 3]) * invT;
                        *(float4*)(op + cc) = o;
                    }
                } else {
                    #pragma unroll
                    for (int cc = 0; cc < 32; cc += 4) {
                        float4 o;
                        o.x = __uint_as_float(r[cc + 0]);
                        o.y = __uint_as_float(r[cc + 1]);
                        o.z = __uint_as_float(r[cc + 2]);
                        o.w = __uint_as_float(r[cc + 3]);
                        *(float4*)(op + cc) = o;
                    }
                }
            }
            if (elect1()) {
                if (rank == 0) mbar_arrive(sbase + 192 + (it & 1) * 8);
                else           mbar_arrive_cluster(sbase + 192 + (it & 1) * 8, 0);
            }
        }
    }

    __syncthreads();
    if (wid == 0) tmem_dealloc_cg2(tmem, 512);
    cluster_sync_all();

#else  // ---------------- naive correct fallback (plain sm_103 pass; unused) ----
    const int cluster = blockIdx.x >> 1;
    const int rank = blockIdx.x & 1;
    const int NCLUST = gridDim.x >> 1;
    const int nt = (cluster < TOTAL) ? (TOTAL - cluster + NCLUST - 1) / NCLUST : 0;
    const float invT = IS_QK ? 1.f / temp[0] : 1.f;
    for (int it = 0; it < nt; it++) {
        const int T = cluster + it * NCLUST;
        const int b = T / TPB, rem = T % TPB;
        const int mypair = rem / NXT2, nx2 = rem % NXT2;
        const int my = mypair * 2 + rank;
        const int m0 = my * 128, n0 = nx2 * 256;
        const char* ca0 = Achunks + (size_t)(b * MT + my) * KST * ACH;
        for (int e = tid; e < 128 * 256; e += 256) {
            int i = e >> 8, j = e & 255;
            const char* cb0 =
                Bchunks + (size_t)(b * NXT2 * 2 + nx2 * 2 + (j >> 7)) * KST * BCH;
            int jj = j & 127;
            float acc = 0.f;
            for (int s = 0; s < KST; s++) {
                const char* ca = ca0 + (size_t)s * ACH;
                const char* cb = cb0 + (size_t)s * BCH;
                for (int k = 0; k < 64; k++) {
                    uint32_t oa = i * 128 + k * 2; oa ^= (oa >> 3) & 0x70;
                    uint32_t ob = jj * 128 + k * 2; ob ^= (ob >> 3) & 0x70;
                    float a, bb;
                    if (IS_QK) {
                        a = __bfloat162float(*(const __nv_bfloat16*)(ca + oa)) +
                            __bfloat162float(*(const __nv_bfloat16*)(ca + 16384 + oa));
                        bb = __bfloat162float(*(const __nv_bfloat16*)(cb + ob)) +
                             __bfloat162float(*(const __nv_bfloat16*)(cb + 16384 + ob));
                    } else {
                        a = __half2float(*(const __half*)(ca + oa));
                        bb = __half2float(*(const __half*)(cb + ob));
                    }
                    acc = fmaf(a, bb, acc);
                }
            }
            float* op = Out + (size_t)b * SQ * LDOUT + (size_t)(m0 + i) * LDOUT + n0 + j;
            *op = IS_QK ? (2.f * acc - g_ksq[b * SK + n0 + j]) * invT : acc;
        }
        __syncthreads();
    }
#endif
}

// ---------------------------------------------------------------------------
// softmax (in-place fp32) + write fp16 chunked W tiles for PV
// ---------------------------------------------------------------------------
__global__ __launch_bounds__(256) void softmax_kernel(float* __restrict__ W) {
    const int rowg = blockIdx.x;
    float* r = W + (size_t)rowg * SK;
    const int tid = threadIdx.x;

    float vals[8];
    *(float4*)(vals) = *(const float4*)(r + tid * 8);
    *(float4*)(vals + 4) = *(const float4*)(r + tid * 8 + 4);
    float m = vals[0];
    #pragma unroll
    for (int i = 1; i < 8; i++) m = fmaxf(m, vals[i]);

    __shared__ float red[8];
    #pragma unroll
    for (int o = 16; o > 0; o >>= 1) m = fmaxf(m, __shfl_xor_sync(0xffffffffu, m, o));
    if ((tid & 31) == 0) red[tid >> 5] = m;
    __syncthreads();
    m = red[0];
    #pragma unroll
    for (int w = 1; w < 8; w++) m = fmaxf(m, red[w]);
    __syncthreads();

    float s = 0.f;
    #pragma unroll
    for (int i = 0; i < 8; i++) {
        vals[i] = __expf(vals[i] - m);
        s += vals[i];
    }
    #pragma unroll
    for (int o = 16; o > 0; o >>= 1) s += __shfl_xor_sync(0xffffffffu, s, o);
    if ((tid & 31) == 0) red[tid >> 5] = s;
    __syncthreads();
    s = red[0];
    #pragma unroll
    for (int w = 1; w < 8; w++) s += red[w];

    const float inv = 1.0f / s;
    #pragma unroll
    for (int i = 0; i < 8; i++) vals[i] *= inv;
    *(float4*)(r + tid * 8) = *(float4*)(vals);
    *(float4*)(r + tid * 8 + 4) = *(float4*)(vals + 4);

    uint32_t w4[4];
    #pragma unroll
    for (int p = 0; p < 4; p++) {
        __half2 hh = __halves2half2(__float2half_rn(vals[2 * p]),
                                    __float2half_rn(vals[2 * p + 1]));
        w4[p] = *(uint32_t*)&hh;
    }
    const int b = rowg >> 11, q = rowg & 2047;
    const int mtile = q >> 7, row = q & 127;
    const int kstage = tid >> 3, colc = (tid * 8) & 63;
    size_t base = (size_t)((b * 16 + mtile) * 32 + kstage) * HCHUNK_B;
    uint32_t off = row * 128 + colc * 2;
    off ^= (off >> 3) & 0x70;
    *(uint4*)(g_Ws + base + off) = make_uint4(w4[0], w4[1], w4[2], w4[3]);
}

// ---------------------------------------------------------------------------
extern "C" void kernel_launch(void* const* d_in, const int* in_sizes, int n_in,
                              void* d_out, int out_size) {
    const float* Q = (const float*)d_in[0];
    const float* K = (const float*)d_in[1];
    const float* V = (const float*)d_in[2];
    const float* T = (const float*)d_in[3];

    float* attended = (float*)d_out;                        // [B,SQ,DH]
    float* weights  = (float*)d_out + (size_t)NB * SQ * DH; // [B,SQ,SK]

    void *qs, *ks, *vs, *ws;
    cudaGetSymbolAddress(&qs, g_Qs);
    cudaGetSymbolAddress(&ks, g_Ks);
    cudaGetSymbolAddress(&vs, g_Vs);
    cudaGetSymbolAddress(&ws, g_Ws);

    cudaFuncSetAttribute((const void*)gemm5_kernel<16, 8, 8, 3, true>,
                         cudaFuncAttributeMaxDynamicSharedMemorySize, SMEM_TOTAL);
    cudaFuncSetAttribute((const void*)gemm5_kernel<16, 2, 32, 6, false>,
                         cudaFuncAttributeMaxDynamicSharedMemorySize, SMEM_TOTAL);

    // 1) fused prep (Q/K splits with fused ksq + V transpose)
    prep_kernel<<<16384, 256>>>(Q, K, V);

    // 2) logits = (2 q.k - ksq)/T  — 512 macro tiles over 74 clusters (148 CTAs)
    gemm5_kernel<16, 8, 8, 3, true><<<148, 256, SMEM_TOTAL>>>(
        (const char*)qs, (const char*)ks, weights, T);

    // 3) softmax in-place + fp16 chunked W
    softmax_kernel<<<NB * SQ, 256>>>(weights);

    // 4) attended = W @ V — 128 macro tiles over 74 clusters
    gemm5_kernel<16, 2, 32, 6, false><<<148, 256, SMEM_TOTAL>>>(
        (const char*)ws, (const char*)vs, attended, nullptr);
}